// round 1
// baseline (speedup 1.0000x reference)
#include <cuda_runtime.h>
#include <cuda_bf16.h>
#include <cstddef>

// Problem dims
#define B_  128
#define S_  256
#define D_  256
#define H_  6
#define HS_ 42
#define DFF_ 1024
#define BS_ (B_ * S_)            // 32768 rows
#define QKVN (3 * H_ * HS_)      // 756
#define HCN  (H_ * HS_)          // 252

// ---------------- scratch (device globals; no allocation allowed) ----------------
__device__ float g_wqkv[D_ * QKVN];          // packed [256, 756]
__device__ float g_qkv [(size_t)BS_ * QKVN]; // [32768, 756]
__device__ float g_hc  [(size_t)BS_ * HCN];  // [32768, 252]
__device__ float g_y1  [(size_t)BS_ * D_];
__device__ float g_ln1 [(size_t)BS_ * D_];
__device__ float g_ffh [(size_t)BS_ * DFF_];
__device__ float g_y2  [(size_t)BS_ * D_];

// ---------------- weight repack: Wq/Wk/Wv [H,D,HS] -> [D, 756] ----------------
__global__ void repack_kernel(const float* __restrict__ Wq, const float* __restrict__ Wk,
                              const float* __restrict__ Wv, float* __restrict__ Wqkv) {
    int idx = blockIdx.x * 256 + threadIdx.x;
    if (idx >= D_ * QKVN) return;
    int d = idx / QKVN, c = idx % QKVN;
    int which = c / HCN, r = c % HCN;
    int h = r / HS_, e = r % HS_;
    const float* W = (which == 0) ? Wq : (which == 1) ? Wk : Wv;
    Wqkv[idx] = W[((size_t)h * D_ + d) * HS_ + e];
}

// ---------------- generic tiled SGEMM: C[M,N] = A[M,K] @ B[K,N] (+epilogue) ----------------
// EPI 0: plain   EPI 1: + bias[col] + res[row,col]   EPI 2: relu(+bias[col])
#define BM 64
#define BN 64
#define BKK 16

template<int EPI>
__global__ void sgemm_kernel(const float* __restrict__ A, const float* __restrict__ B,
                             const float* __restrict__ bias, const float* __restrict__ res,
                             float* __restrict__ C, int M, int N, int K) {
    __shared__ float As[BKK][BM + 4];   // stride 68 floats (16B-aligned rows)
    __shared__ float Bs[BKK][BN + 4];
    int tid = threadIdx.x;
    int tx = tid & 15, ty = tid >> 4;       // 16x16 thread grid, 4x4 micro-tile
    int m0 = blockIdx.y * BM;
    int n0 = blockIdx.x * BN;

    float acc[4][4];
    #pragma unroll
    for (int i = 0; i < 4; i++)
        #pragma unroll
        for (int j = 0; j < 4; j++) acc[i][j] = 0.f;

    for (int k0 = 0; k0 < K; k0 += BKK) {
        // A tile 64x16 (coalesced along K)
        #pragma unroll
        for (int i = 0; i < 4; i++) {
            int idx = tid + i * 256;
            int kk = idx & 15, r = idx >> 4;
            int kg = k0 + kk;
            float v = 0.f;
            if (kg < K) v = A[(size_t)(m0 + r) * K + kg];
            As[kk][r] = v;
        }
        // B tile 16x64 (coalesced along N)
        #pragma unroll
        for (int i = 0; i < 4; i++) {
            int idx = tid + i * 256;
            int c = idx & 63, kk = idx >> 6;
            int kg = k0 + kk, ng = n0 + c;
            float v = 0.f;
            if (kg < K && ng < N) v = B[(size_t)kg * N + ng];
            Bs[kk][c] = v;
        }
        __syncthreads();
        #pragma unroll
        for (int kk = 0; kk < BKK; kk++) {
            float4 a4 = *(const float4*)&As[kk][ty * 4];
            float4 b4 = *(const float4*)&Bs[kk][tx * 4];
            float a[4] = {a4.x, a4.y, a4.z, a4.w};
            float b[4] = {b4.x, b4.y, b4.z, b4.w};
            #pragma unroll
            for (int i = 0; i < 4; i++)
                #pragma unroll
                for (int j = 0; j < 4; j++)
                    acc[i][j] = fmaf(a[i], b[j], acc[i][j]);
        }
        __syncthreads();
    }

    #pragma unroll
    for (int i = 0; i < 4; i++) {
        int row = m0 + ty * 4 + i;
        #pragma unroll
        for (int j = 0; j < 4; j++) {
            int col = n0 + tx * 4 + j;
            if (col < N) {
                float v = acc[i][j];
                if (EPI == 1) v += bias[col] + res[(size_t)row * N + col];
                if (EPI == 2) v = fmaxf(v + bias[col], 0.f);
                C[(size_t)row * N + col] = v;
            }
        }
    }
}

// ---------------- causal attention, one CTA per (b,h), online softmax ----------------
// qkv row layout: [q(0..251) | k(252..503) | v(504..755)], head h at h*42
__global__ void attn_kernel(const float* __restrict__ qkv, float* __restrict__ headcat) {
    extern __shared__ float sm[];
    float* Ks = sm;                 // [256*42]
    float* Vs = sm + S_ * HS_;      // [256*42]
    int bh = blockIdx.x;
    int b = bh / H_, h = bh % H_;
    int tid = threadIdx.x;
    const size_t rowbase = (size_t)b * S_ * QKVN;

    for (int idx = tid; idx < S_ * HS_; idx += 256) {
        int t = idx / HS_, e = idx - t * HS_;
        size_t g = rowbase + (size_t)t * QKVN + h * HS_ + e;
        Ks[idx] = qkv[g + HCN];
        Vs[idx] = qkv[g + 2 * HCN];
    }
    __syncthreads();

    int s = tid;  // query row for this thread
    float q[HS_];
    {
        size_t g = rowbase + (size_t)s * QKVN + h * HS_;
        #pragma unroll
        for (int e = 0; e < HS_; e++) q[e] = qkv[g + e];
    }
    const float scale = rsqrtf((float)HS_);
    float m = -1e30f, l = 0.f;
    float o[HS_];
    #pragma unroll
    for (int e = 0; e < HS_; e++) o[e] = 0.f;

    for (int t = 0; t <= s; t++) {   // causal; warp stays broadcast-coherent
        const float* kr = &Ks[t * HS_];
        float dot = 0.f;
        #pragma unroll
        for (int e = 0; e < HS_; e++) dot = fmaf(q[e], kr[e], dot);
        float p = dot * scale;
        float nm = fmaxf(m, p);
        float f = __expf(m - nm);
        float w = __expf(p - nm);
        l = l * f + w;
        const float* vr = &Vs[t * HS_];
        #pragma unroll
        for (int e = 0; e < HS_; e++) o[e] = fmaf(o[e], f, w * vr[e]);
        m = nm;
    }
    float inv = 1.f / l;
    size_t og = ((size_t)b * S_ + s) * HCN + h * HS_;
    #pragma unroll
    for (int e = 0; e < HS_; e++) headcat[og + e] = o[e] * inv;
}

// ---------------- LayerNorm: one warp per row of 256 ----------------
__global__ void ln_kernel(const float* __restrict__ in, const float* __restrict__ gam,
                          const float* __restrict__ bet, float* __restrict__ out) {
    int warp = threadIdx.x >> 5, lane = threadIdx.x & 31;
    size_t row = (size_t)blockIdx.x * 8 + warp;
    const float* p = in + row * D_;
    float v[8];
    float4 a = *(const float4*)&p[lane * 8];
    float4 c = *(const float4*)&p[lane * 8 + 4];
    v[0]=a.x; v[1]=a.y; v[2]=a.z; v[3]=a.w;
    v[4]=c.x; v[5]=c.y; v[6]=c.z; v[7]=c.w;
    float sum = 0.f;
    #pragma unroll
    for (int i = 0; i < 8; i++) sum += v[i];
    #pragma unroll
    for (int off = 16; off; off >>= 1) sum += __shfl_xor_sync(0xffffffffu, sum, off);
    float mu = sum * (1.f / 256.f);
    float s2 = 0.f;
    #pragma unroll
    for (int i = 0; i < 8; i++) { float d = v[i] - mu; s2 = fmaf(d, d, s2); }
    #pragma unroll
    for (int off = 16; off; off >>= 1) s2 += __shfl_xor_sync(0xffffffffu, s2, off);
    float rs = rsqrtf(s2 * (1.f / 256.f) + 1e-5f);
    float* po = out + row * D_;
    #pragma unroll
    for (int i = 0; i < 8; i++) {
        int col = lane * 8 + i;
        po[col] = (v[i] - mu) * rs * gam[col] + bet[col];
    }
}

// ---------------- launch ----------------
extern "C" void kernel_launch(void* const* d_in, const int* in_sizes, int n_in,
                              void* d_out, int out_size) {
    const float* x      = (const float*)d_in[0];
    const float* Wq     = (const float*)d_in[1];
    const float* Wk     = (const float*)d_in[2];
    const float* Wv     = (const float*)d_in[3];
    const float* Wproj  = (const float*)d_in[4];
    const float* bproj  = (const float*)d_in[5];
    const float* ln1_g  = (const float*)d_in[6];
    const float* ln1_b  = (const float*)d_in[7];
    const float* W1     = (const float*)d_in[8];
    const float* b1     = (const float*)d_in[9];
    const float* W2     = (const float*)d_in[10];
    const float* b2     = (const float*)d_in[11];
    const float* ln2_g  = (const float*)d_in[12];
    const float* ln2_b  = (const float*)d_in[13];
    float* out = (float*)d_out;

    float *wqkv, *qkvp, *hc, *y1, *ln1, *ffh, *y2;
    cudaGetSymbolAddress((void**)&wqkv, g_wqkv);
    cudaGetSymbolAddress((void**)&qkvp, g_qkv);
    cudaGetSymbolAddress((void**)&hc,   g_hc);
    cudaGetSymbolAddress((void**)&y1,   g_y1);
    cudaGetSymbolAddress((void**)&ln1,  g_ln1);
    cudaGetSymbolAddress((void**)&ffh,  g_ffh);
    cudaGetSymbolAddress((void**)&y2,   g_y2);

    const int attn_smem = 2 * S_ * HS_ * (int)sizeof(float);  // 86016 B
    cudaFuncSetAttribute(attn_kernel, cudaFuncAttributeMaxDynamicSharedMemorySize, attn_smem);

    dim3 blk(256);
    // 1) pack QKV weights
    repack_kernel<<<(D_ * QKVN + 255) / 256, blk>>>(Wq, Wk, Wv, wqkv);
    // 2) QKV projection: [32768,256] @ [256,756]
    sgemm_kernel<0><<<dim3((QKVN + BN - 1) / BN, BS_ / BM), blk>>>(
        x, wqkv, nullptr, nullptr, qkvp, BS_, QKVN, D_);
    // 3) causal attention
    attn_kernel<<<B_ * H_, blk, attn_smem>>>(qkvp, hc);
    // 4) output proj + bias + residual(x): [32768,252] @ [252,256]
    sgemm_kernel<1><<<dim3(D_ / BN, BS_ / BM), blk>>>(
        hc, Wproj, bproj, x, y1, BS_, D_, HCN);
    // 5) LN1
    ln_kernel<<<BS_ / 8, blk>>>(y1, ln1_g, ln1_b, ln1);
    // 6) FFN up + ReLU: [32768,256] @ [256,1024]
    sgemm_kernel<2><<<dim3(DFF_ / BN, BS_ / BM), blk>>>(
        ln1, W1, b1, nullptr, ffh, BS_, DFF_, D_);
    // 7) FFN down + bias + residual(ln1): [32768,1024] @ [1024,256]
    sgemm_kernel<1><<<dim3(D_ / BN, BS_ / BM), blk>>>(
        ffh, W2, b2, ln1, y2, BS_, D_, DFF_);
    // 8) LN2 -> out
    ln_kernel<<<BS_ / 8, blk>>>(y2, ln2_g, ln2_b, out);
    (void)in_sizes; (void)n_in; (void)out_size;
}

// round 2
// speedup vs baseline: 1.3604x; 1.3604x over previous
#include <cuda_runtime.h>
#include <cuda_bf16.h>
#include <cstddef>

// Problem dims
#define B_  128
#define S_  256
#define D_  256
#define H_  6
#define HS_ 42
#define DFF_ 1024
#define BS_ (B_ * S_)            // 32768 rows
#define QKVN (3 * H_ * HS_)      // 756
#define HCN  (H_ * HS_)          // 252

typedef unsigned long long ull;

// ---------------- scratch (device globals; no allocation allowed) ----------------
__device__ float g_wqkv[D_ * QKVN];          // packed [256, 756]
__device__ float g_qkv [(size_t)BS_ * QKVN]; // [32768, 756]
__device__ float g_hc  [(size_t)BS_ * HCN];  // [32768, 252]
__device__ float g_y1  [(size_t)BS_ * D_];
__device__ float g_ln1 [(size_t)BS_ * D_];
__device__ float g_ffh [(size_t)BS_ * DFF_];
__device__ float g_y2  [(size_t)BS_ * D_];

// ---------------- weight repack: Wq/Wk/Wv [H,D,HS] -> [D, 756] ----------------
__global__ void repack_kernel(const float* __restrict__ Wq, const float* __restrict__ Wk,
                              const float* __restrict__ Wv, float* __restrict__ Wqkv) {
    int idx = blockIdx.x * 256 + threadIdx.x;
    if (idx >= D_ * QKVN) return;
    int d = idx / QKVN, c = idx % QKVN;
    int which = c / HCN, r = c % HCN;
    int h = r / HS_, e = r % HS_;
    const float* W = (which == 0) ? Wq : (which == 1) ? Wk : Wv;
    Wqkv[idx] = W[((size_t)h * D_ + d) * HS_ + e];
}

// ---------------- packed f32x2 helpers ----------------
#define FMA2(d, a, b) asm("fma.rn.f32x2 %0, %1, %2, %0;" : "+l"(d) : "l"(a), "l"(b))
#define PACK2(d, f)   asm("mov.b64 %0, {%1, %1};" : "=l"(d) : "f"(f))
#define UNPK2(lo, hi, d) asm("mov.b64 {%0, %1}, %2;" : "=f"(lo), "=f"(hi) : "l"(d))

__device__ __forceinline__ void cp16(void* smem_dst, const void* gsrc, int pred) {
    unsigned sdst = (unsigned)__cvta_generic_to_shared(smem_dst);
    int n = pred ? 16 : 0;
    asm volatile("cp.async.cg.shared.global [%0], [%1], 16, %2;"
                 :: "r"(sdst), "l"(gsrc), "r"(n));
}

// ---------------- 128x128x16 fp32x2 GEMM: C[M,N] = A[M,K] @ B[K,N] (+epilogue) ----------------
// EPI 0: plain   EPI 1: + bias[col] + res[row,col]   EPI 2: relu(+bias[col])
template<int EPI>
__global__ __launch_bounds__(256, 2)
void gemm128_kernel(const float* __restrict__ A, const float* __restrict__ B,
                    const float* __restrict__ bias, const float* __restrict__ res,
                    float* __restrict__ C, int M, int N, int K) {
    __shared__ float As[2][16][128];
    __shared__ float Bs[2][16][128];

    const int tid = threadIdx.x;
    const int tx = tid & 15, ty = tid >> 4;
    const int ty4 = ty * 4, tx4 = tx * 4;
    const int m0 = blockIdx.y * 128;
    const int n0 = blockIdx.x * 128;
    const int T = (K + 15) / 16;

    ull acc[8][4];
    #pragma unroll
    for (int i = 0; i < 8; i++)
        #pragma unroll
        for (int j = 0; j < 4; j++) acc[i][j] = 0ull;

    // A-load mapping: f = tid*2 + i -> row = f>>2 (0..127), k4 = f&3
    const int arow = tid >> 1;                 // (tid*2)>>2
    const int ak4_0 = (tid * 2) & 3;           // i=0
    const int ak4_1 = (tid * 2 + 1) & 3;       // i=1
    // B-load mapping: f = i*256 + tid -> krow = f>>5, col4 = f&31
    const int bk0 = tid >> 5,  bc0 = (tid & 31) * 4;
    const int bk1 = 8 + (tid >> 5), bc1 = (tid & 31) * 4;

    // ---- preload tile 0 ----
    {
        int kg0 = ak4_0 * 4, kg1 = ak4_1 * 4;
        float4 av0 = (kg0 < K) ? *(const float4*)&A[(size_t)(m0 + arow) * K + kg0]
                               : make_float4(0.f, 0.f, 0.f, 0.f);
        float4 av1 = (kg1 < K) ? *(const float4*)&A[(size_t)(m0 + arow) * K + kg1]
                               : make_float4(0.f, 0.f, 0.f, 0.f);
        As[0][ak4_0 * 4 + 0][arow] = av0.x; As[0][ak4_0 * 4 + 1][arow] = av0.y;
        As[0][ak4_0 * 4 + 2][arow] = av0.z; As[0][ak4_0 * 4 + 3][arow] = av0.w;
        As[0][ak4_1 * 4 + 0][arow] = av1.x; As[0][ak4_1 * 4 + 1][arow] = av1.y;
        As[0][ak4_1 * 4 + 2][arow] = av1.z; As[0][ak4_1 * 4 + 3][arow] = av1.w;
        cp16(&Bs[0][bk0][bc0], &B[(size_t)bk0 * N + n0 + bc0], (bk0 < K) && (n0 + bc0 < N));
        cp16(&Bs[0][bk1][bc1], &B[(size_t)bk1 * N + n0 + bc1], (bk1 < K) && (n0 + bc1 < N));
        asm volatile("cp.async.commit_group;");
    }

    for (int t = 0; t < T; t++) {
        asm volatile("cp.async.wait_group 0;");
        __syncthreads();
        const int cur = t & 1, nxt = cur ^ 1;
        const int nk0 = (t + 1) * 16;
        float4 av0, av1;
        bool have_next = (t + 1 < T);
        if (have_next) {
            // issue next B tile (overlaps with compute)
            cp16(&Bs[nxt][bk0][bc0], &B[(size_t)(nk0 + bk0) * N + n0 + bc0],
                 (nk0 + bk0 < K) && (n0 + bc0 < N));
            cp16(&Bs[nxt][bk1][bc1], &B[(size_t)(nk0 + bk1) * N + n0 + bc1],
                 (nk0 + bk1 < K) && (n0 + bc1 < N));
            asm volatile("cp.async.commit_group;");
            int kg0 = nk0 + ak4_0 * 4, kg1 = nk0 + ak4_1 * 4;
            av0 = (kg0 < K) ? *(const float4*)&A[(size_t)(m0 + arow) * K + kg0]
                            : make_float4(0.f, 0.f, 0.f, 0.f);
            av1 = (kg1 < K) ? *(const float4*)&A[(size_t)(m0 + arow) * K + kg1]
                            : make_float4(0.f, 0.f, 0.f, 0.f);
        }
        // ---- compute 16 k-steps ----
        #pragma unroll
        for (int kk = 0; kk < 16; kk++) {
            float4 a0 = *(const float4*)&As[cur][kk][ty4];
            float4 a1 = *(const float4*)&As[cur][kk][ty4 + 64];
            ulonglong2 bq0 = *(const ulonglong2*)&Bs[cur][kk][tx4];
            ulonglong2 bq1 = *(const ulonglong2*)&Bs[cur][kk][tx4 + 64];
            ull bp[4] = {bq0.x, bq0.y, bq1.x, bq1.y};
            float as[8] = {a0.x, a0.y, a0.z, a0.w, a1.x, a1.y, a1.z, a1.w};
            #pragma unroll
            for (int i = 0; i < 8; i++) {
                ull ap; PACK2(ap, as[i]);
                #pragma unroll
                for (int j = 0; j < 4; j++) FMA2(acc[i][j], ap, bp[j]);
            }
        }
        if (have_next) {
            As[nxt][ak4_0 * 4 + 0][arow] = av0.x; As[nxt][ak4_0 * 4 + 1][arow] = av0.y;
            As[nxt][ak4_0 * 4 + 2][arow] = av0.z; As[nxt][ak4_0 * 4 + 3][arow] = av0.w;
            As[nxt][ak4_1 * 4 + 0][arow] = av1.x; As[nxt][ak4_1 * 4 + 1][arow] = av1.y;
            As[nxt][ak4_1 * 4 + 2][arow] = av1.z; As[nxt][ak4_1 * 4 + 3][arow] = av1.w;
        }
    }

    // ---- epilogue ----
    #pragma unroll
    for (int i = 0; i < 8; i++) {
        int row = m0 + ty4 + ((i < 4) ? i : 60 + i);
        #pragma unroll
        for (int j = 0; j < 4; j++) {
            int col = n0 + tx4 + ((j & 1) * 2) + ((j >> 1) * 64);
            if (col < N) {
                float lo, hi; UNPK2(lo, hi, acc[i][j]);
                if (EPI == 1) {
                    float2 r2 = *(const float2*)&res[(size_t)row * N + col];
                    lo += bias[col]     + r2.x;
                    hi += bias[col + 1] + r2.y;
                } else if (EPI == 2) {
                    lo = fmaxf(lo + bias[col], 0.f);
                    hi = fmaxf(hi + bias[col + 1], 0.f);
                }
                *(float2*)&C[(size_t)row * N + col] = make_float2(lo, hi);
            }
        }
    }
}

// ---------------- causal attention, one CTA per (b,h), online softmax ----------------
__global__ void attn_kernel(const float* __restrict__ qkv, float* __restrict__ headcat) {
    extern __shared__ float sm[];
    float* Ks = sm;                 // [256*42]
    float* Vs = sm + S_ * HS_;      // [256*42]
    int bh = blockIdx.x;
    int b = bh / H_, h = bh % H_;
    int tid = threadIdx.x;
    const size_t rowbase = (size_t)b * S_ * QKVN;

    for (int idx = tid; idx < S_ * HS_; idx += 256) {
        int t = idx / HS_, e = idx - t * HS_;
        size_t g = rowbase + (size_t)t * QKVN + h * HS_ + e;
        Ks[idx] = qkv[g + HCN];
        Vs[idx] = qkv[g + 2 * HCN];
    }
    __syncthreads();

    int s = tid;  // query row for this thread
    float q[HS_];
    {
        size_t g = rowbase + (size_t)s * QKVN + h * HS_;
        #pragma unroll
        for (int e = 0; e < HS_; e++) q[e] = qkv[g + e];
    }
    const float scale = rsqrtf((float)HS_);
    float m = -1e30f, l = 0.f;
    float o[HS_];
    #pragma unroll
    for (int e = 0; e < HS_; e++) o[e] = 0.f;

    for (int t = 0; t <= s; t++) {   // causal; warp stays broadcast-coherent
        const float* kr = &Ks[t * HS_];
        float dot = 0.f;
        #pragma unroll
        for (int e = 0; e < HS_; e++) dot = fmaf(q[e], kr[e], dot);
        float p = dot * scale;
        float nm = fmaxf(m, p);
        float f = __expf(m - nm);
        float w = __expf(p - nm);
        l = l * f + w;
        const float* vr = &Vs[t * HS_];
        #pragma unroll
        for (int e = 0; e < HS_; e++) o[e] = fmaf(o[e], f, w * vr[e]);
        m = nm;
    }
    float inv = 1.f / l;
    size_t og = ((size_t)b * S_ + s) * HCN + h * HS_;
    #pragma unroll
    for (int e = 0; e < HS_; e++) headcat[og + e] = o[e] * inv;
}

// ---------------- LayerNorm: one warp per row of 256 ----------------
__global__ void ln_kernel(const float* __restrict__ in, const float* __restrict__ gam,
                          const float* __restrict__ bet, float* __restrict__ out) {
    int warp = threadIdx.x >> 5, lane = threadIdx.x & 31;
    size_t row = (size_t)blockIdx.x * 8 + warp;
    const float* p = in + row * D_;
    float v[8];
    float4 a = *(const float4*)&p[lane * 8];
    float4 c = *(const float4*)&p[lane * 8 + 4];
    v[0]=a.x; v[1]=a.y; v[2]=a.z; v[3]=a.w;
    v[4]=c.x; v[5]=c.y; v[6]=c.z; v[7]=c.w;
    float sum = 0.f;
    #pragma unroll
    for (int i = 0; i < 8; i++) sum += v[i];
    #pragma unroll
    for (int off = 16; off; off >>= 1) sum += __shfl_xor_sync(0xffffffffu, sum, off);
    float mu = sum * (1.f / 256.f);
    float s2 = 0.f;
    #pragma unroll
    for (int i = 0; i < 8; i++) { float d = v[i] - mu; s2 = fmaf(d, d, s2); }
    #pragma unroll
    for (int off = 16; off; off >>= 1) s2 += __shfl_xor_sync(0xffffffffu, s2, off);
    float rs = rsqrtf(s2 * (1.f / 256.f) + 1e-5f);
    float* po = out + row * D_;
    #pragma unroll
    for (int i = 0; i < 8; i++) {
        int col = lane * 8 + i;
        po[col] = (v[i] - mu) * rs * gam[col] + bet[col];
    }
}

// ---------------- launch ----------------
extern "C" void kernel_launch(void* const* d_in, const int* in_sizes, int n_in,
                              void* d_out, int out_size) {
    const float* x      = (const float*)d_in[0];
    const float* Wq     = (const float*)d_in[1];
    const float* Wk     = (const float*)d_in[2];
    const float* Wv     = (const float*)d_in[3];
    const float* Wproj  = (const float*)d_in[4];
    const float* bproj  = (const float*)d_in[5];
    const float* ln1_g  = (const float*)d_in[6];
    const float* ln1_b  = (const float*)d_in[7];
    const float* W1     = (const float*)d_in[8];
    const float* b1     = (const float*)d_in[9];
    const float* W2     = (const float*)d_in[10];
    const float* b2     = (const float*)d_in[11];
    const float* ln2_g  = (const float*)d_in[12];
    const float* ln2_b  = (const float*)d_in[13];
    float* out = (float*)d_out;

    float *wqkv, *qkvp, *hc, *y1, *ln1, *ffh, *y2;
    cudaGetSymbolAddress((void**)&wqkv, g_wqkv);
    cudaGetSymbolAddress((void**)&qkvp, g_qkv);
    cudaGetSymbolAddress((void**)&hc,   g_hc);
    cudaGetSymbolAddress((void**)&y1,   g_y1);
    cudaGetSymbolAddress((void**)&ln1,  g_ln1);
    cudaGetSymbolAddress((void**)&ffh,  g_ffh);
    cudaGetSymbolAddress((void**)&y2,   g_y2);

    const int attn_smem = 2 * S_ * HS_ * (int)sizeof(float);  // 86016 B
    cudaFuncSetAttribute(attn_kernel, cudaFuncAttributeMaxDynamicSharedMemorySize, attn_smem);

    dim3 blk(256);
    const int MT = BS_ / 128;   // 256 row tiles
    // 1) pack QKV weights
    repack_kernel<<<(D_ * QKVN + 255) / 256, blk>>>(Wq, Wk, Wv, wqkv);
    // 2) QKV projection: [32768,256] @ [256,756]
    gemm128_kernel<0><<<dim3((QKVN + 127) / 128, MT), blk>>>(
        x, wqkv, nullptr, nullptr, qkvp, BS_, QKVN, D_);
    // 3) causal attention
    attn_kernel<<<B_ * H_, blk, attn_smem>>>(qkvp, hc);
    // 4) output proj + bias + residual(x): [32768,252] @ [252,256]
    gemm128_kernel<1><<<dim3(D_ / 128, MT), blk>>>(
        hc, Wproj, bproj, x, y1, BS_, D_, HCN);
    // 5) LN1
    ln_kernel<<<BS_ / 8, blk>>>(y1, ln1_g, ln1_b, ln1);
    // 6) FFN up + ReLU: [32768,256] @ [256,1024]
    gemm128_kernel<2><<<dim3(DFF_ / 128, MT), blk>>>(
        ln1, W1, b1, nullptr, ffh, BS_, DFF_, D_);
    // 7) FFN down + bias + residual(ln1): [32768,1024] @ [1024,256]
    gemm128_kernel<1><<<dim3(D_ / 128, MT), blk>>>(
        ffh, W2, b2, ln1, y2, BS_, D_, DFF_);
    // 8) LN2 -> out
    ln_kernel<<<BS_ / 8, blk>>>(y2, ln2_g, ln2_b, out);
    (void)in_sizes; (void)n_in; (void)out_size;
}

// round 4
// speedup vs baseline: 1.6150x; 1.1872x over previous
#include <cuda_runtime.h>
#include <cuda_bf16.h>
#include <cstdint>
#include <cstddef>

// ---------------- problem dims ----------------
#define B_   128
#define S_   256
#define D_   256
#define H_   6
#define HS_  42
#define DFF_ 1024
#define BS_  (B_ * S_)     // 32768
#define QKVP 768           // padded 3*H*HS (756 -> 768)
#define HCN  252           // H*HS

// ---------------- scratch (device globals) ----------------
__device__ float          g_qkv [(size_t)BS_ * QKVP];     // fp32 qkv (padded)
__device__ __nv_bfloat16  g_xs_h[(size_t)BS_ * D_];
__device__ __nv_bfloat16  g_xs_l[(size_t)BS_ * D_];
__device__ __nv_bfloat16  g_hc_h[(size_t)BS_ * 256];      // headcat split, K padded 252->256
__device__ __nv_bfloat16  g_hc_l[(size_t)BS_ * 256];
__device__ float          g_y1  [(size_t)BS_ * D_];
__device__ float          g_ln1 [(size_t)BS_ * D_];
__device__ __nv_bfloat16  g_l1_h[(size_t)BS_ * D_];
__device__ __nv_bfloat16  g_l1_l[(size_t)BS_ * D_];
__device__ __nv_bfloat16  g_ff_h[(size_t)BS_ * DFF_];
__device__ __nv_bfloat16  g_ff_l[(size_t)BS_ * DFF_];
__device__ float          g_y2  [(size_t)BS_ * D_];
// weights (transposed [N,K] split planes)
__device__ __nv_bfloat16  g_wqkv_h[QKVP * D_],  g_wqkv_l[QKVP * D_];
__device__ __nv_bfloat16  g_wpj_h [D_ * 256],   g_wpj_l [D_ * 256];
__device__ __nv_bfloat16  g_w1_h  [DFF_ * D_],  g_w1_l  [DFF_ * D_];
__device__ __nv_bfloat16  g_w2_h  [D_ * DFF_],  g_w2_l  [D_ * DFF_];

// ---------------- helpers ----------------
__device__ __forceinline__ void split2(float v, __nv_bfloat16& h, __nv_bfloat16& l) {
    h = __float2bfloat16_rn(v);
    l = __float2bfloat16_rn(v - __bfloat162float(h));
}
__device__ __forceinline__ uint32_t smem_u32(const void* p) {
    uint32_t a;
    asm("{ .reg .u64 t; cvta.to.shared.u64 t, %1; cvt.u32.u64 %0, t; }" : "=r"(a) : "l"(p));
    return a;
}
__device__ __forceinline__ void cp16(uint32_t sdst, const void* g) {
    asm volatile("cp.async.cg.shared.global [%0], [%1], 16;" :: "r"(sdst), "l"(g));
}
#define LDSM4(r0, r1, r2, r3, a) \
    asm volatile("ldmatrix.sync.aligned.m8n8.x4.shared.b16 {%0,%1,%2,%3}, [%4];" \
                 : "=r"(r0), "=r"(r1), "=r"(r2), "=r"(r3) : "r"(a))
#define MMA16816(d, a, b) \
    asm volatile("mma.sync.aligned.m16n8k16.row.col.f32.bf16.bf16.f32 " \
                 "{%0,%1,%2,%3},{%4,%5,%6,%7},{%8,%9},{%0,%1,%2,%3};" \
                 : "+f"((d)[0]), "+f"((d)[1]), "+f"((d)[2]), "+f"((d)[3]) \
                 : "r"((a)[0]), "r"((a)[1]), "r"((a)[2]), "r"((a)[3]), \
                   "r"((b)[0]), "r"((b)[1]))

// ---------------- conversion kernels ----------------
__global__ void split_x_kernel(const float* __restrict__ x,
                               __nv_bfloat16* __restrict__ oh, __nv_bfloat16* __restrict__ ol,
                               size_t n) {
    size_t i = (size_t)blockIdx.x * 256 + threadIdx.x;
    if (i < n) split2(x[i], oh[i], ol[i]);
}
// Wq/Wk/Wv [H,D,HS] -> transposed split [768, 256]
__global__ void wqkv_kernel(const float* __restrict__ Wq, const float* __restrict__ Wk,
                            const float* __restrict__ Wv,
                            __nv_bfloat16* __restrict__ oh, __nv_bfloat16* __restrict__ ol) {
    int i = blockIdx.x * 256 + threadIdx.x;
    if (i >= QKVP * D_) return;
    int n = i / D_, k = i % D_;
    float v = 0.f;
    if (n < 756) {
        int which = n / HCN, r = n % HCN, h = r / HS_, e = r % HS_;
        const float* W = (which == 0) ? Wq : (which == 1) ? Wk : Wv;
        v = W[((size_t)h * D_ + k) * HS_ + e];
    }
    split2(v, oh[i], ol[i]);
}
// src [Ksrc, Nout] -> out [Nout, Kp] transposed split (pad K with zeros)
__global__ void tsplit_kernel(const float* __restrict__ src,
                              __nv_bfloat16* __restrict__ oh, __nv_bfloat16* __restrict__ ol,
                              int Ksrc, int Nout, int Kp) {
    int i = blockIdx.x * 256 + threadIdx.x;
    if (i >= Nout * Kp) return;
    int n = i / Kp, k = i % Kp;
    float v = (k < Ksrc) ? src[(size_t)k * Nout + n] : 0.f;
    split2(v, oh[i], ol[i]);
}

// ---------------- mma.sync bf16 GEMM: C[M,N] = (Ah+Al)[M,K] @ (Bh+Bl)^T[N,K] ----------------
// EPI 0: Cf = v    EPI 1: Cf = v + bias[col] + res[row,col]
// EPI 3: split(relu(v + bias[col])) -> Ch/Cl planes
#define STG_BYTES 32768       // A tile 16KB + B tile 16KB (128 rows x 128B, 64 bf16/row slab)
template<int EPI>
__global__ __launch_bounds__(256, 1)
void mma_gemm(const __nv_bfloat16* __restrict__ Ah, const __nv_bfloat16* __restrict__ Al,
              const __nv_bfloat16* __restrict__ Bh, const __nv_bfloat16* __restrict__ Bl,
              const float* __restrict__ bias, const float* __restrict__ res,
              float* __restrict__ Cf, __nv_bfloat16* __restrict__ Ch,
              __nv_bfloat16* __restrict__ Cl, int M, int N, int K) {
    extern __shared__ char smem[];
    const uint32_t sbase = smem_u32(smem);
    const uint32_t DATA = (sbase + 1023) & ~1023u;
    const int tid = threadIdx.x, lane = tid & 31, wid = tid >> 5;
    const int wm = (wid & 1) * 64;      // warp m-offset
    const int wn = (wid >> 1) * 32;     // warp n-offset
    const int m0 = blockIdx.y * 128, n0 = blockIdx.x * 128;
    const int nslab = K / 64;
    const int S = 3 * nslab;

    float acc[4][4][4];
    #pragma unroll
    for (int i = 0; i < 4; i++)
        #pragma unroll
        for (int j = 0; j < 4; j++)
            #pragma unroll
            for (int r = 0; r < 4; r++) acc[i][j][r] = 0.f;

    // cp.async mapping: 1024 16B-chunks per operand tile, 4 per thread
    int arow[4], asw[4], acol[4];
    #pragma unroll
    for (int i = 0; i < 4; i++) {
        int c = tid + i * 256;
        int r = c >> 3, cc = c & 7;
        arow[i] = r; acol[i] = cc * 8;
        asw[i] = r * 128 + ((cc * 16) ^ ((r & 7) * 16));
    }

    auto load_slab = [&](int s, int stage) {
        int pass = s / nslab, j = s - pass * nslab;
        int k0 = j * 64;
        const __nv_bfloat16* Ap = (pass == 2) ? Al : Ah;
        const __nv_bfloat16* Bp = (pass == 1) ? Bl : Bh;
        const __nv_bfloat16* As = Ap + (size_t)m0 * K + k0;
        const __nv_bfloat16* Bs = Bp + (size_t)n0 * K + k0;
        uint32_t ab = DATA + stage * STG_BYTES;
        uint32_t bb = ab + 16384;
        #pragma unroll
        for (int i = 0; i < 4; i++)
            cp16(ab + asw[i], As + (size_t)arow[i] * K + acol[i]);
        #pragma unroll
        for (int i = 0; i < 4; i++)
            cp16(bb + asw[i], Bs + (size_t)arow[i] * K + acol[i]);
        asm volatile("cp.async.commit_group;");
    };

    // per-lane ldmatrix address offsets (within a tile), for k-chunk kk added later
    const int lg = lane >> 3, l8 = lane & 7;
    // A: g0: m0..7/k0  g1: m8..15/k0  g2: m0..7/k8  g3: m8..15/k8
    const int a_r = (lg & 1) * 8 + l8;       // + mbase
    const int a_kadd = (lg >> 1) * 8;
    // B: g0: n0..7/k0  g1: n0..7/k8  g2: n8..15/k0  g3: n8..15/k8
    const int b_r = ((lg >> 1) & 1) * 8 + l8; // + nbase
    const int b_kadd = (lg & 1) * 8;

    load_slab(0, 0);
    if (S > 1) load_slab(1, 1);

    for (int s = 0; s < S; s++) {
        if (s + 2 < S) load_slab(s + 2, (s + 2) % 3);
        int rem = S - 1 - s;
        if (rem >= 2)      asm volatile("cp.async.wait_group 2;");
        else if (rem == 1) asm volatile("cp.async.wait_group 1;");
        else               asm volatile("cp.async.wait_group 0;");
        __syncthreads();

        const uint32_t ab = DATA + (s % 3) * STG_BYTES;
        const uint32_t bb = ab + 16384;
        #pragma unroll
        for (int ks = 0; ks < 4; ks++) {
            const int kk = ks * 16;
            uint32_t afr[4][4];
            #pragma unroll
            for (int mf = 0; mf < 4; mf++) {
                int r = wm + mf * 16 + a_r;
                int kc = kk + a_kadd;
                uint32_t addr = ab + r * 128 + ((kc * 2) ^ ((r & 7) * 16));
                LDSM4(afr[mf][0], afr[mf][1], afr[mf][2], afr[mf][3], addr);
            }
            uint32_t bfr[4][2];
            #pragma unroll
            for (int nb = 0; nb < 2; nb++) {
                int r = wn + nb * 16 + b_r;
                int kc = kk + b_kadd;
                uint32_t addr = bb + r * 128 + ((kc * 2) ^ ((r & 7) * 16));
                uint32_t r0, r1, r2, r3;
                LDSM4(r0, r1, r2, r3, addr);
                bfr[nb * 2][0] = r0; bfr[nb * 2][1] = r1;
                bfr[nb * 2 + 1][0] = r2; bfr[nb * 2 + 1][1] = r3;
            }
            #pragma unroll
            for (int mf = 0; mf < 4; mf++)
                #pragma unroll
                for (int nf = 0; nf < 4; nf++)
                    MMA16816(acc[mf][nf], afr[mf], bfr[nf]);
        }
        __syncthreads();
    }

    // ---- epilogue: write accumulators directly ----
    const int qrow = lane >> 2, qcol = (lane & 3) * 2;
    #pragma unroll
    for (int mf = 0; mf < 4; mf++) {
        #pragma unroll
        for (int nf = 0; nf < 4; nf++) {
            int row0 = m0 + wm + mf * 16 + qrow;
            int col  = n0 + wn + nf * 8 + qcol;
            float* d = acc[mf][nf];
            #pragma unroll
            for (int half = 0; half < 2; half++) {
                int row = row0 + half * 8;
                float v0 = d[half * 2], v1 = d[half * 2 + 1];
                size_t go = (size_t)row * N + col;
                if (EPI == 0) {
                    *(float2*)&Cf[go] = make_float2(v0, v1);
                } else if (EPI == 1) {
                    float2 r2 = *(const float2*)&res[go];
                    float2 b2 = *(const float2*)&bias[col];
                    *(float2*)&Cf[go] = make_float2(v0 + b2.x + r2.x, v1 + b2.y + r2.y);
                } else {
                    float2 b2 = *(const float2*)&bias[col];
                    v0 = fmaxf(v0 + b2.x, 0.f);
                    v1 = fmaxf(v1 + b2.y, 0.f);
                    __nv_bfloat16 h0, l0, h1, l1;
                    split2(v0, h0, l0); split2(v1, h1, l1);
                    *(__nv_bfloat162*)&Ch[go] = __nv_bfloat162(h0, h1);
                    *(__nv_bfloat162*)&Cl[go] = __nv_bfloat162(l0, l1);
                }
            }
        }
    }
}

// ---------------- causal attention (qkv fp32 stride 768) -> split hc planes ----------------
__global__ void attn_kernel(const float* __restrict__ qkv,
                            __nv_bfloat16* __restrict__ hch, __nv_bfloat16* __restrict__ hcl) {
    extern __shared__ float sm[];
    float* Ks = sm;
    float* Vs = sm + S_ * HS_;
    int bh = blockIdx.x;
    int b = bh / H_, h = bh % H_;
    int tid = threadIdx.x;
    const size_t rowbase = (size_t)b * S_ * QKVP;

    for (int idx = tid; idx < S_ * HS_; idx += 256) {
        int t = idx / HS_, e = idx - t * HS_;
        size_t g = rowbase + (size_t)t * QKVP + h * HS_ + e;
        Ks[idx] = qkv[g + HCN];
        Vs[idx] = qkv[g + 2 * HCN];
    }
    __syncthreads();

    int s = tid;
    float q[HS_];
    {
        size_t g = rowbase + (size_t)s * QKVP + h * HS_;
        #pragma unroll
        for (int e = 0; e < HS_; e++) q[e] = qkv[g + e];
    }
    const float scale = rsqrtf((float)HS_);
    float m = -1e30f, l = 0.f;
    float o[HS_];
    #pragma unroll
    for (int e = 0; e < HS_; e++) o[e] = 0.f;

    for (int t = 0; t <= s; t++) {
        const float* kr = &Ks[t * HS_];
        float dot = 0.f;
        #pragma unroll
        for (int e = 0; e < HS_; e++) dot = fmaf(q[e], kr[e], dot);
        float p = dot * scale;
        float nm = fmaxf(m, p);
        float f = __expf(m - nm);
        float w = __expf(p - nm);
        l = l * f + w;
        const float* vr = &Vs[t * HS_];
        #pragma unroll
        for (int e = 0; e < HS_; e++) o[e] = fmaf(o[e], f, w * vr[e]);
        m = nm;
    }
    float inv = 1.f / l;
    size_t og = ((size_t)b * S_ + s) * 256 + h * HS_;
    #pragma unroll
    for (int e = 0; e < HS_; e++) {
        __nv_bfloat16 hh, ll;
        split2(o[e] * inv, hh, ll);
        hch[og + e] = hh; hcl[og + e] = ll;
    }
    if (h == 0) {   // zero K-pad cols 252..255
        size_t pg = ((size_t)b * S_ + s) * 256 + 252;
        #pragma unroll
        for (int e = 0; e < 4; e++) { hch[pg + e] = __nv_bfloat16(0.f); hcl[pg + e] = __nv_bfloat16(0.f); }
    }
}

// ---------------- LayerNorm (optional split-plane outputs) ----------------
__global__ void ln_kernel(const float* __restrict__ in, const float* __restrict__ gam,
                          const float* __restrict__ bet, float* __restrict__ out,
                          __nv_bfloat16* __restrict__ oh, __nv_bfloat16* __restrict__ ol) {
    int warp = threadIdx.x >> 5, lane = threadIdx.x & 31;
    size_t row = (size_t)blockIdx.x * 8 + warp;
    const float* p = in + row * D_;
    float v[8];
    float4 a = *(const float4*)&p[lane * 8];
    float4 c = *(const float4*)&p[lane * 8 + 4];
    v[0]=a.x; v[1]=a.y; v[2]=a.z; v[3]=a.w;
    v[4]=c.x; v[5]=c.y; v[6]=c.z; v[7]=c.w;
    float sum = 0.f;
    #pragma unroll
    for (int i = 0; i < 8; i++) sum += v[i];
    #pragma unroll
    for (int off = 16; off; off >>= 1) sum += __shfl_xor_sync(0xffffffffu, sum, off);
    float mu = sum * (1.f / 256.f);
    float s2 = 0.f;
    #pragma unroll
    for (int i = 0; i < 8; i++) { float d = v[i] - mu; s2 = fmaf(d, d, s2); }
    #pragma unroll
    for (int off = 16; off; off >>= 1) s2 += __shfl_xor_sync(0xffffffffu, s2, off);
    float rs = rsqrtf(s2 * (1.f / 256.f) + 1e-5f);
    float* po = out + row * D_;
    #pragma unroll
    for (int i = 0; i < 8; i++) {
        int col = lane * 8 + i;
        float r = (v[i] - mu) * rs * gam[col] + bet[col];
        po[col] = r;
        if (oh) {
            __nv_bfloat16 hh, ll;
            split2(r, hh, ll);
            oh[row * D_ + col] = hh; ol[row * D_ + col] = ll;
        }
    }
}

// ---------------- launch ----------------
extern "C" void kernel_launch(void* const* d_in, const int* in_sizes, int n_in,
                              void* d_out, int out_size) {
    const float* x      = (const float*)d_in[0];
    const float* Wq     = (const float*)d_in[1];
    const float* Wk     = (const float*)d_in[2];
    const float* Wv     = (const float*)d_in[3];
    const float* Wproj  = (const float*)d_in[4];
    const float* bproj  = (const float*)d_in[5];
    const float* ln1_g  = (const float*)d_in[6];
    const float* ln1_b  = (const float*)d_in[7];
    const float* W1     = (const float*)d_in[8];
    const float* b1     = (const float*)d_in[9];
    const float* W2     = (const float*)d_in[10];
    const float* b2     = (const float*)d_in[11];
    const float* ln2_g  = (const float*)d_in[12];
    const float* ln2_b  = (const float*)d_in[13];
    float* out = (float*)d_out;

    float *qkvp, *y1, *ln1, *y2;
    __nv_bfloat16 *xs_h, *xs_l, *hc_h, *hc_l, *l1_h, *l1_l, *ff_h, *ff_l;
    __nv_bfloat16 *wqkv_h, *wqkv_l, *wpj_h, *wpj_l, *w1_h, *w1_l, *w2_h, *w2_l;
    cudaGetSymbolAddress((void**)&qkvp, g_qkv);
    cudaGetSymbolAddress((void**)&y1,   g_y1);
    cudaGetSymbolAddress((void**)&ln1,  g_ln1);
    cudaGetSymbolAddress((void**)&y2,   g_y2);
    cudaGetSymbolAddress((void**)&xs_h, g_xs_h); cudaGetSymbolAddress((void**)&xs_l, g_xs_l);
    cudaGetSymbolAddress((void**)&hc_h, g_hc_h); cudaGetSymbolAddress((void**)&hc_l, g_hc_l);
    cudaGetSymbolAddress((void**)&l1_h, g_l1_h); cudaGetSymbolAddress((void**)&l1_l, g_l1_l);
    cudaGetSymbolAddress((void**)&ff_h, g_ff_h); cudaGetSymbolAddress((void**)&ff_l, g_ff_l);
    cudaGetSymbolAddress((void**)&wqkv_h, g_wqkv_h); cudaGetSymbolAddress((void**)&wqkv_l, g_wqkv_l);
    cudaGetSymbolAddress((void**)&wpj_h, g_wpj_h);   cudaGetSymbolAddress((void**)&wpj_l, g_wpj_l);
    cudaGetSymbolAddress((void**)&w1_h, g_w1_h);     cudaGetSymbolAddress((void**)&w1_l, g_w1_l);
    cudaGetSymbolAddress((void**)&w2_h, g_w2_h);     cudaGetSymbolAddress((void**)&w2_l, g_w2_l);

    const int gemm_smem = 1024 + 3 * STG_BYTES;   // align slack + 3 stages
    cudaFuncSetAttribute(mma_gemm<0>, cudaFuncAttributeMaxDynamicSharedMemorySize, gemm_smem);
    cudaFuncSetAttribute(mma_gemm<1>, cudaFuncAttributeMaxDynamicSharedMemorySize, gemm_smem);
    cudaFuncSetAttribute(mma_gemm<3>, cudaFuncAttributeMaxDynamicSharedMemorySize, gemm_smem);
    const int attn_smem = 2 * S_ * HS_ * (int)sizeof(float);
    cudaFuncSetAttribute(attn_kernel, cudaFuncAttributeMaxDynamicSharedMemorySize, attn_smem);

    dim3 blk(256);
    // conversions
    split_x_kernel<<<(BS_ * D_ + 255) / 256, blk>>>(x, xs_h, xs_l, (size_t)BS_ * D_);
    wqkv_kernel<<<(QKVP * D_ + 255) / 256, blk>>>(Wq, Wk, Wv, wqkv_h, wqkv_l);
    tsplit_kernel<<<(D_ * 256 + 255) / 256, blk>>>(Wproj, wpj_h, wpj_l, HCN, D_, 256);
    tsplit_kernel<<<(DFF_ * D_ + 255) / 256, blk>>>(W1, w1_h, w1_l, D_, DFF_, D_);
    tsplit_kernel<<<(D_ * DFF_ + 255) / 256, blk>>>(W2, w2_h, w2_l, DFF_, D_, DFF_);

    // 1) QKV: [32768,256] @ [768,256]^T -> qkv fp32
    mma_gemm<0><<<dim3(QKVP / 128, BS_ / 128), blk, gemm_smem>>>(
        xs_h, xs_l, wqkv_h, wqkv_l, nullptr, nullptr, qkvp, nullptr, nullptr, BS_, QKVP, D_);
    // 2) attention -> hc split planes
    attn_kernel<<<B_ * H_, blk, attn_smem>>>(qkvp, hc_h, hc_l);
    // 3) proj: hc @ Wproj^T + bproj + x -> y1
    mma_gemm<1><<<dim3(D_ / 128, BS_ / 128), blk, gemm_smem>>>(
        hc_h, hc_l, wpj_h, wpj_l, bproj, x, y1, nullptr, nullptr, BS_, D_, 256);
    // 4) LN1 -> ln1 fp32 + split planes
    ln_kernel<<<BS_ / 8, blk>>>(y1, ln1_g, ln1_b, ln1, l1_h, l1_l);
    // 5) FFN up: relu(ln1 @ W1^T + b1) -> ffh split planes
    mma_gemm<3><<<dim3(DFF_ / 128, BS_ / 128), blk, gemm_smem>>>(
        l1_h, l1_l, w1_h, w1_l, b1, nullptr, nullptr, ff_h, ff_l, BS_, DFF_, D_);
    // 6) FFN down: ffh @ W2^T + b2 + ln1 -> y2
    mma_gemm<1><<<dim3(D_ / 128, BS_ / 128), blk, gemm_smem>>>(
        ff_h, ff_l, w2_h, w2_l, b2, ln1, y2, nullptr, nullptr, BS_, D_, DFF_);
    // 7) LN2 -> out
    ln_kernel<<<BS_ / 8, blk>>>(y2, ln2_g, ln2_b, out, nullptr, nullptr);
    (void)in_sizes; (void)n_in; (void)out_size;
}

// round 5
// speedup vs baseline: 1.7725x; 1.0975x over previous
#include <cuda_runtime.h>
#include <cuda_bf16.h>
#include <cstdint>
#include <cstddef>

// ---------------- problem dims ----------------
#define B_   128
#define S_   256
#define D_   256
#define H_   6
#define HS_  42
#define DFF_ 1024
#define BS_  (B_ * S_)     // 32768
#define QKVP 768           // padded 3*H*HS (756 -> 768)
#define HCN  252           // H*HS

// ---------------- scratch (device globals) ----------------
__device__ float          g_qkv [(size_t)BS_ * QKVP];
__device__ __nv_bfloat16  g_xs_h[(size_t)BS_ * D_];
__device__ __nv_bfloat16  g_xs_l[(size_t)BS_ * D_];
__device__ __nv_bfloat16  g_hc_h[(size_t)BS_ * 256];
__device__ __nv_bfloat16  g_hc_l[(size_t)BS_ * 256];
__device__ float          g_y1  [(size_t)BS_ * D_];
__device__ float          g_ln1 [(size_t)BS_ * D_];
__device__ __nv_bfloat16  g_l1_h[(size_t)BS_ * D_];
__device__ __nv_bfloat16  g_l1_l[(size_t)BS_ * D_];
__device__ __nv_bfloat16  g_ff_h[(size_t)BS_ * DFF_];
__device__ __nv_bfloat16  g_ff_l[(size_t)BS_ * DFF_];
__device__ float          g_y2  [(size_t)BS_ * D_];
__device__ __nv_bfloat16  g_wqkv_h[QKVP * D_],  g_wqkv_l[QKVP * D_];
__device__ __nv_bfloat16  g_wpj_h [D_ * 256],   g_wpj_l [D_ * 256];
__device__ __nv_bfloat16  g_w1_h  [DFF_ * D_],  g_w1_l  [DFF_ * D_];
__device__ __nv_bfloat16  g_w2_h  [D_ * DFF_],  g_w2_l  [D_ * DFF_];

// ---------------- helpers ----------------
__device__ __forceinline__ void split2(float v, __nv_bfloat16& h, __nv_bfloat16& l) {
    h = __float2bfloat16_rn(v);
    l = __float2bfloat16_rn(v - __bfloat162float(h));
}
__device__ __forceinline__ uint32_t smem_u32(const void* p) {
    uint32_t a;
    asm("{ .reg .u64 t; cvta.to.shared.u64 t, %1; cvt.u32.u64 %0, t; }" : "=r"(a) : "l"(p));
    return a;
}
__device__ __forceinline__ void cp16(uint32_t sdst, const void* g) {
    asm volatile("cp.async.cg.shared.global [%0], [%1], 16;" :: "r"(sdst), "l"(g));
}
#define LDSM4(r0, r1, r2, r3, a) \
    asm volatile("ldmatrix.sync.aligned.m8n8.x4.shared.b16 {%0,%1,%2,%3}, [%4];" \
                 : "=r"(r0), "=r"(r1), "=r"(r2), "=r"(r3) : "r"(a))
#define MMA16816(d, a, b) \
    asm volatile("mma.sync.aligned.m16n8k16.row.col.f32.bf16.bf16.f32 " \
                 "{%0,%1,%2,%3},{%4,%5,%6,%7},{%8,%9},{%0,%1,%2,%3};" \
                 : "+f"((d)[0]), "+f"((d)[1]), "+f"((d)[2]), "+f"((d)[3]) \
                 : "r"((a)[0]), "r"((a)[1]), "r"((a)[2]), "r"((a)[3]), \
                   "r"((b)[0]), "r"((b)[1]))

// ---------------- conversion kernels ----------------
__global__ void split_x_kernel(const float* __restrict__ x,
                               __nv_bfloat16* __restrict__ oh, __nv_bfloat16* __restrict__ ol,
                               size_t n) {
    size_t i = (size_t)blockIdx.x * 256 + threadIdx.x;
    if (i < n) split2(x[i], oh[i], ol[i]);
}
__global__ void wqkv_kernel(const float* __restrict__ Wq, const float* __restrict__ Wk,
                            const float* __restrict__ Wv,
                            __nv_bfloat16* __restrict__ oh, __nv_bfloat16* __restrict__ ol) {
    int i = blockIdx.x * 256 + threadIdx.x;
    if (i >= QKVP * D_) return;
    int n = i / D_, k = i % D_;
    float v = 0.f;
    if (n < 756) {
        int which = n / HCN, r = n % HCN, h = r / HS_, e = r % HS_;
        const float* W = (which == 0) ? Wq : (which == 1) ? Wk : Wv;
        v = W[((size_t)h * D_ + k) * HS_ + e];
    }
    split2(v, oh[i], ol[i]);
}
__global__ void tsplit_kernel(const float* __restrict__ src,
                              __nv_bfloat16* __restrict__ oh, __nv_bfloat16* __restrict__ ol,
                              int Ksrc, int Nout, int Kp) {
    int i = blockIdx.x * 256 + threadIdx.x;
    if (i >= Nout * Kp) return;
    int n = i / Kp, k = i % Kp;
    float v = (k < Ksrc) ? src[(size_t)k * Nout + n] : 0.f;
    split2(v, oh[i], ol[i]);
}

// ---------------- fused 3-product mma.sync GEMM ----------------
// C[M,N] = (Ah+Al)[M,K] @ (Bh+Bl)^T[N,K] dropping Al*Bl.
// Per 32-wide k-slab, hi|lo planes packed in one 128B smem row: [hi 64B | lo 64B].
// EPI 0: Cf = v    EPI 1: Cf = v + bias[col] + res[row,col]
// EPI 3: split(relu(v + bias[col])) -> Ch/Cl planes
#define STG_BYTES 32768       // A combined 16KB + B combined 16KB
template<int EPI>
__global__ __launch_bounds__(256, 2)
void mma_gemm(const __nv_bfloat16* __restrict__ Ah, const __nv_bfloat16* __restrict__ Al,
              const __nv_bfloat16* __restrict__ Bh, const __nv_bfloat16* __restrict__ Bl,
              const float* __restrict__ bias, const float* __restrict__ res,
              float* __restrict__ Cf, __nv_bfloat16* __restrict__ Ch,
              __nv_bfloat16* __restrict__ Cl, int M, int N, int K) {
    extern __shared__ char smem[];
    const uint32_t sbase = smem_u32(smem);
    const uint32_t DATA = (sbase + 1023) & ~1023u;
    const int tid = threadIdx.x, lane = tid & 31, wid = tid >> 5;
    const int wm = (wid & 1) * 64;      // warp m-offset
    const int wn = (wid >> 1) * 32;     // warp n-offset
    const int m0 = blockIdx.y * 128, n0 = blockIdx.x * 128;
    const int S = K / 32;               // 32-wide k-slabs

    float acc[4][4][4];
    #pragma unroll
    for (int i = 0; i < 4; i++)
        #pragma unroll
        for (int j = 0; j < 4; j++)
            #pragma unroll
            for (int r = 0; r < 4; r++) acc[i][j][r] = 0.f;

    // cp.async mapping: per operand 1024 16B-chunks (128 rows x 8 chunks).
    // chunk cc<4 -> hi plane cols cc*8 ; cc>=4 -> lo plane cols (cc-4)*8
    int crow[4], csw[4], chi[4], ccol[4];
    #pragma unroll
    for (int i = 0; i < 4; i++) {
        int c = tid + i * 256;
        int r = c >> 3, cc = c & 7;
        crow[i] = r;
        chi[i] = (cc < 4);
        ccol[i] = (cc & 3) * 8;
        csw[i] = r * 128 + ((cc * 16) ^ ((r & 7) * 16));
    }

    auto load_slab = [&](int s, int stage) {
        int k0 = s * 32;
        uint32_t ab = DATA + stage * STG_BYTES;
        uint32_t bb = ab + 16384;
        #pragma unroll
        for (int i = 0; i < 4; i++) {
            const __nv_bfloat16* src = chi[i] ? Ah : Al;
            cp16(ab + csw[i], src + (size_t)(m0 + crow[i]) * K + k0 + ccol[i]);
        }
        #pragma unroll
        for (int i = 0; i < 4; i++) {
            const __nv_bfloat16* src = chi[i] ? Bh : Bl;
            cp16(bb + csw[i], src + (size_t)(n0 + crow[i]) * K + k0 + ccol[i]);
        }
        asm volatile("cp.async.commit_group;");
    };

    // per-lane ldmatrix fragment mapping (same as validated R3 kernel)
    const int lg = lane >> 3, l8 = lane & 7;
    const int a_r = (lg & 1) * 8 + l8;
    const int a_kadd = (lg >> 1) * 8;
    const int b_r = ((lg >> 1) & 1) * 8 + l8;
    const int b_kadd = (lg & 1) * 8;

    load_slab(0, 0);

    for (int s = 0; s < S; s++) {
        if (s + 1 < S) {
            load_slab(s + 1, (s + 1) & 1);
            asm volatile("cp.async.wait_group 1;");
        } else {
            asm volatile("cp.async.wait_group 0;");
        }
        __syncthreads();

        const uint32_t ab = DATA + (s & 1) * STG_BYTES;
        const uint32_t bb = ab + 16384;
        #pragma unroll
        for (int ks = 0; ks < 2; ks++) {
            const int kbyte = (ks * 16 + 0) * 2;
            uint32_t afr[4][4];
            // Ah fragments
            #pragma unroll
            for (int mf = 0; mf < 4; mf++) {
                int r = wm + mf * 16 + a_r;
                int bc = kbyte + a_kadd * 2;           // hi plane: bytes 0..63
                uint32_t addr = ab + r * 128 + (bc ^ ((r & 7) * 16));
                LDSM4(afr[mf][0], afr[mf][1], afr[mf][2], afr[mf][3], addr);
            }
            // Bh + Bl fragments
            uint32_t bh[4][2], bl[4][2];
            #pragma unroll
            for (int nb = 0; nb < 2; nb++) {
                int r = wn + nb * 16 + b_r;
                int bc = kbyte + b_kadd * 2;
                uint32_t addr_h = bb + r * 128 + (bc ^ ((r & 7) * 16));
                uint32_t addr_l = bb + r * 128 + ((bc + 64) ^ ((r & 7) * 16));
                uint32_t r0, r1, r2, r3;
                LDSM4(r0, r1, r2, r3, addr_h);
                bh[nb * 2][0] = r0; bh[nb * 2][1] = r1;
                bh[nb * 2 + 1][0] = r2; bh[nb * 2 + 1][1] = r3;
                LDSM4(r0, r1, r2, r3, addr_l);
                bl[nb * 2][0] = r0; bl[nb * 2][1] = r1;
                bl[nb * 2 + 1][0] = r2; bl[nb * 2 + 1][1] = r3;
            }
            // Ah*Bh and Ah*Bl
            #pragma unroll
            for (int mf = 0; mf < 4; mf++)
                #pragma unroll
                for (int nf = 0; nf < 4; nf++)
                    MMA16816(acc[mf][nf], afr[mf], bh[nf]);
            #pragma unroll
            for (int mf = 0; mf < 4; mf++)
                #pragma unroll
                for (int nf = 0; nf < 4; nf++)
                    MMA16816(acc[mf][nf], afr[mf], bl[nf]);
            // Al fragments (reuse afr), then Al*Bh
            #pragma unroll
            for (int mf = 0; mf < 4; mf++) {
                int r = wm + mf * 16 + a_r;
                int bc = kbyte + a_kadd * 2 + 64;      // lo plane: bytes 64..127
                uint32_t addr = ab + r * 128 + (bc ^ ((r & 7) * 16));
                LDSM4(afr[mf][0], afr[mf][1], afr[mf][2], afr[mf][3], addr);
            }
            #pragma unroll
            for (int mf = 0; mf < 4; mf++)
                #pragma unroll
                for (int nf = 0; nf < 4; nf++)
                    MMA16816(acc[mf][nf], afr[mf], bh[nf]);
        }
        __syncthreads();
    }

    // ---- epilogue: write accumulators directly ----
    const int qrow = lane >> 2, qcol = (lane & 3) * 2;
    #pragma unroll
    for (int mf = 0; mf < 4; mf++) {
        #pragma unroll
        for (int nf = 0; nf < 4; nf++) {
            int row0 = m0 + wm + mf * 16 + qrow;
            int col  = n0 + wn + nf * 8 + qcol;
            float* d = acc[mf][nf];
            #pragma unroll
            for (int half = 0; half < 2; half++) {
                int row = row0 + half * 8;
                float v0 = d[half * 2], v1 = d[half * 2 + 1];
                size_t go = (size_t)row * N + col;
                if (EPI == 0) {
                    *(float2*)&Cf[go] = make_float2(v0, v1);
                } else if (EPI == 1) {
                    float2 r2 = *(const float2*)&res[go];
                    float2 b2 = *(const float2*)&bias[col];
                    *(float2*)&Cf[go] = make_float2(v0 + b2.x + r2.x, v1 + b2.y + r2.y);
                } else {
                    float2 b2 = *(const float2*)&bias[col];
                    v0 = fmaxf(v0 + b2.x, 0.f);
                    v1 = fmaxf(v1 + b2.y, 0.f);
                    __nv_bfloat16 h0, l0, h1, l1;
                    split2(v0, h0, l0); split2(v1, h1, l1);
                    *(__nv_bfloat162*)&Ch[go] = __nv_bfloat162(h0, h1);
                    *(__nv_bfloat162*)&Cl[go] = __nv_bfloat162(l0, l1);
                }
            }
        }
    }
}

// ---------------- causal attention (qkv fp32 stride 768) -> split hc planes ----------------
__global__ void attn_kernel(const float* __restrict__ qkv,
                            __nv_bfloat16* __restrict__ hch, __nv_bfloat16* __restrict__ hcl) {
    extern __shared__ float sm[];
    float* Ks = sm;
    float* Vs = sm + S_ * HS_;
    int bh = blockIdx.x;
    int b = bh / H_, h = bh % H_;
    int tid = threadIdx.x;
    const size_t rowbase = (size_t)b * S_ * QKVP;

    for (int idx = tid; idx < S_ * HS_; idx += 256) {
        int t = idx / HS_, e = idx - t * HS_;
        size_t g = rowbase + (size_t)t * QKVP + h * HS_ + e;
        Ks[idx] = qkv[g + HCN];
        Vs[idx] = qkv[g + 2 * HCN];
    }
    __syncthreads();

    int s = tid;
    float q[HS_];
    {
        size_t g = rowbase + (size_t)s * QKVP + h * HS_;
        #pragma unroll
        for (int e = 0; e < HS_; e++) q[e] = qkv[g + e];
    }
    const float scale = rsqrtf((float)HS_);
    float m = -1e30f, l = 0.f;
    float o[HS_];
    #pragma unroll
    for (int e = 0; e < HS_; e++) o[e] = 0.f;

    for (int t = 0; t <= s; t++) {
        const float* kr = &Ks[t * HS_];
        float dot = 0.f;
        #pragma unroll
        for (int e = 0; e < HS_; e++) dot = fmaf(q[e], kr[e], dot);
        float p = dot * scale;
        float nm = fmaxf(m, p);
        float f = __expf(m - nm);
        float w = __expf(p - nm);
        l = l * f + w;
        const float* vr = &Vs[t * HS_];
        #pragma unroll
        for (int e = 0; e < HS_; e++) o[e] = fmaf(o[e], f, w * vr[e]);
        m = nm;
    }
    float inv = 1.f / l;
    size_t og = ((size_t)b * S_ + s) * 256 + h * HS_;
    #pragma unroll
    for (int e = 0; e < HS_; e++) {
        __nv_bfloat16 hh, ll;
        split2(o[e] * inv, hh, ll);
        hch[og + e] = hh; hcl[og + e] = ll;
    }
    if (h == 0) {
        size_t pg = ((size_t)b * S_ + s) * 256 + 252;
        #pragma unroll
        for (int e = 0; e < 4; e++) { hch[pg + e] = __nv_bfloat16(0.f); hcl[pg + e] = __nv_bfloat16(0.f); }
    }
}

// ---------------- LayerNorm (optional split-plane outputs) ----------------
__global__ void ln_kernel(const float* __restrict__ in, const float* __restrict__ gam,
                          const float* __restrict__ bet, float* __restrict__ out,
                          __nv_bfloat16* __restrict__ oh, __nv_bfloat16* __restrict__ ol) {
    int warp = threadIdx.x >> 5, lane = threadIdx.x & 31;
    size_t row = (size_t)blockIdx.x * 8 + warp;
    const float* p = in + row * D_;
    float v[8];
    float4 a = *(const float4*)&p[lane * 8];
    float4 c = *(const float4*)&p[lane * 8 + 4];
    v[0]=a.x; v[1]=a.y; v[2]=a.z; v[3]=a.w;
    v[4]=c.x; v[5]=c.y; v[6]=c.z; v[7]=c.w;
    float sum = 0.f;
    #pragma unroll
    for (int i = 0; i < 8; i++) sum += v[i];
    #pragma unroll
    for (int off = 16; off; off >>= 1) sum += __shfl_xor_sync(0xffffffffu, sum, off);
    float mu = sum * (1.f / 256.f);
    float s2 = 0.f;
    #pragma unroll
    for (int i = 0; i < 8; i++) { float d = v[i] - mu; s2 = fmaf(d, d, s2); }
    #pragma unroll
    for (int off = 16; off; off >>= 1) s2 += __shfl_xor_sync(0xffffffffu, s2, off);
    float rs = rsqrtf(s2 * (1.f / 256.f) + 1e-5f);
    float* po = out + row * D_;
    #pragma unroll
    for (int i = 0; i < 8; i++) {
        int col = lane * 8 + i;
        float r = (v[i] - mu) * rs * gam[col] + bet[col];
        po[col] = r;
        if (oh) {
            __nv_bfloat16 hh, ll;
            split2(r, hh, ll);
            oh[row * D_ + col] = hh; ol[row * D_ + col] = ll;
        }
    }
}

// ---------------- launch ----------------
extern "C" void kernel_launch(void* const* d_in, const int* in_sizes, int n_in,
                              void* d_out, int out_size) {
    const float* x      = (const float*)d_in[0];
    const float* Wq     = (const float*)d_in[1];
    const float* Wk     = (const float*)d_in[2];
    const float* Wv     = (const float*)d_in[3];
    const float* Wproj  = (const float*)d_in[4];
    const float* bproj  = (const float*)d_in[5];
    const float* ln1_g  = (const float*)d_in[6];
    const float* ln1_b  = (const float*)d_in[7];
    const float* W1     = (const float*)d_in[8];
    const float* b1     = (const float*)d_in[9];
    const float* W2     = (const float*)d_in[10];
    const float* b2     = (const float*)d_in[11];
    const float* ln2_g  = (const float*)d_in[12];
    const float* ln2_b  = (const float*)d_in[13];
    float* out = (float*)d_out;

    float *qkvp, *y1, *ln1, *y2;
    __nv_bfloat16 *xs_h, *xs_l, *hc_h, *hc_l, *l1_h, *l1_l, *ff_h, *ff_l;
    __nv_bfloat16 *wqkv_h, *wqkv_l, *wpj_h, *wpj_l, *w1_h, *w1_l, *w2_h, *w2_l;
    cudaGetSymbolAddress((void**)&qkvp, g_qkv);
    cudaGetSymbolAddress((void**)&y1,   g_y1);
    cudaGetSymbolAddress((void**)&ln1,  g_ln1);
    cudaGetSymbolAddress((void**)&y2,   g_y2);
    cudaGetSymbolAddress((void**)&xs_h, g_xs_h); cudaGetSymbolAddress((void**)&xs_l, g_xs_l);
    cudaGetSymbolAddress((void**)&hc_h, g_hc_h); cudaGetSymbolAddress((void**)&hc_l, g_hc_l);
    cudaGetSymbolAddress((void**)&l1_h, g_l1_h); cudaGetSymbolAddress((void**)&l1_l, g_l1_l);
    cudaGetSymbolAddress((void**)&ff_h, g_ff_h); cudaGetSymbolAddress((void**)&ff_l, g_ff_l);
    cudaGetSymbolAddress((void**)&wqkv_h, g_wqkv_h); cudaGetSymbolAddress((void**)&wqkv_l, g_wqkv_l);
    cudaGetSymbolAddress((void**)&wpj_h, g_wpj_h);   cudaGetSymbolAddress((void**)&wpj_l, g_wpj_l);
    cudaGetSymbolAddress((void**)&w1_h, g_w1_h);     cudaGetSymbolAddress((void**)&w1_l, g_w1_l);
    cudaGetSymbolAddress((void**)&w2_h, g_w2_h);     cudaGetSymbolAddress((void**)&w2_l, g_w2_l);

    const int gemm_smem = 1024 + 2 * STG_BYTES;   // align slack + 2 stages = 66.5KB
    cudaFuncSetAttribute(mma_gemm<0>, cudaFuncAttributeMaxDynamicSharedMemorySize, gemm_smem);
    cudaFuncSetAttribute(mma_gemm<1>, cudaFuncAttributeMaxDynamicSharedMemorySize, gemm_smem);
    cudaFuncSetAttribute(mma_gemm<3>, cudaFuncAttributeMaxDynamicSharedMemorySize, gemm_smem);
    const int attn_smem = 2 * S_ * HS_ * (int)sizeof(float);
    cudaFuncSetAttribute(attn_kernel, cudaFuncAttributeMaxDynamicSharedMemorySize, attn_smem);

    dim3 blk(256);
    // conversions
    split_x_kernel<<<(BS_ * D_ + 255) / 256, blk>>>(x, xs_h, xs_l, (size_t)BS_ * D_);
    wqkv_kernel<<<(QKVP * D_ + 255) / 256, blk>>>(Wq, Wk, Wv, wqkv_h, wqkv_l);
    tsplit_kernel<<<(D_ * 256 + 255) / 256, blk>>>(Wproj, wpj_h, wpj_l, HCN, D_, 256);
    tsplit_kernel<<<(DFF_ * D_ + 255) / 256, blk>>>(W1, w1_h, w1_l, D_, DFF_, D_);
    tsplit_kernel<<<(D_ * DFF_ + 255) / 256, blk>>>(W2, w2_h, w2_l, DFF_, D_, DFF_);

    // 1) QKV: [32768,256] @ [768,256]^T -> qkv fp32
    mma_gemm<0><<<dim3(QKVP / 128, BS_ / 128), blk, gemm_smem>>>(
        xs_h, xs_l, wqkv_h, wqkv_l, nullptr, nullptr, qkvp, nullptr, nullptr, BS_, QKVP, D_);
    // 2) attention -> hc split planes
    attn_kernel<<<B_ * H_, blk, attn_smem>>>(qkvp, hc_h, hc_l);
    // 3) proj: hc @ Wproj^T + bproj + x -> y1
    mma_gemm<1><<<dim3(D_ / 128, BS_ / 128), blk, gemm_smem>>>(
        hc_h, hc_l, wpj_h, wpj_l, bproj, x, y1, nullptr, nullptr, BS_, D_, 256);
    // 4) LN1 -> ln1 fp32 + split planes
    ln_kernel<<<BS_ / 8, blk>>>(y1, ln1_g, ln1_b, ln1, l1_h, l1_l);
    // 5) FFN up: relu(ln1 @ W1^T + b1) -> ffh split planes
    mma_gemm<3><<<dim3(DFF_ / 128, BS_ / 128), blk, gemm_smem>>>(
        l1_h, l1_l, w1_h, w1_l, b1, nullptr, nullptr, ff_h, ff_l, BS_, DFF_, D_);
    // 6) FFN down: ffh @ W2^T + b2 + ln1 -> y2
    mma_gemm<1><<<dim3(D_ / 128, BS_ / 128), blk, gemm_smem>>>(
        ff_h, ff_l, w2_h, w2_l, b2, ln1, y2, nullptr, nullptr, BS_, D_, DFF_);
    // 7) LN2 -> out
    ln_kernel<<<BS_ / 8, blk>>>(y2, ln2_g, ln2_b, out, nullptr, nullptr);
    (void)in_sizes; (void)n_in; (void)out_size;
}